// round 2
// baseline (speedup 1.0000x reference)
#include <cuda_runtime.h>

#define NE   8192
#define DD   64
#define NTOK 16384
#define BETA  0.25f
#define DECAY 0.99f
#define EPSC  1e-5f

// output layout (concatenated, float32)
#define OZQ   0
#define OLOSS 1048576
#define OW    1048577
#define OCS   1572865
#define OEA   1581057

// device scratch (no allocations allowed)
__device__ float g_wsq[NE];
__device__ unsigned long long g_part[2][NTOK];
__device__ float g_enc[NE];
__device__ float g_emb[NE * DD];
__device__ float g_loss;
__device__ float g_nsum;

// ---------------------------------------------------------------- zero pass
__global__ void k_zero() {
    int i = blockIdx.x * blockDim.x + threadIdx.x;
    if (i < NE * DD) g_emb[i] = 0.f;
    if (i < NE)      g_enc[i] = 0.f;
    if (i == 0) { g_loss = 0.f; g_nsum = 0.f; }
}

// ---------------------------------------------------------------- |w_k|^2
__global__ void k_wsq(const float* __restrict__ w) {
    int gt   = blockIdx.x * blockDim.x + threadIdx.x;
    int row  = gt >> 5;
    int lane = gt & 31;
    if (row >= NE) return;
    const float* r = w + row * DD;
    float a = r[lane], b2 = r[lane + 32];
    float s = a * a + b2 * b2;
    #pragma unroll
    for (int o = 16; o; o >>= 1) s += __shfl_down_sync(0xFFFFFFFFu, s, o);
    if (lane == 0) g_wsq[row] = s;
}

// ---------------------------------------------------------------- argmin
#define TILE  64
#define PITCH 66   // padded row pitch (floats); 66*4 bytes keeps 8B alignment

__device__ __forceinline__ unsigned long long dup2(float x) {
    unsigned long long r;
    asm("mov.b64 %0, {%1, %1};" : "=l"(r) : "f"(x));
    return r;
}
__device__ __forceinline__ void fma2(unsigned long long& d,
                                     unsigned long long a,
                                     unsigned long long b) {
    asm("fma.rn.f32x2 %0, %1, %2, %0;" : "+l"(d) : "l"(a), "l"(b));
}

__global__ __launch_bounds__(128)
void k_argmin(const float* __restrict__ z, const float* __restrict__ w) {
    __shared__ float sw[DD * PITCH];   // channel-major code tile
    __shared__ float swsq[TILE];

    int tid   = threadIdx.x;
    int n     = blockIdx.x * 128 + tid;    // token id
    int split = blockIdx.y;                 // code split (0/1)
    int b  = n >> 10;
    int hw = n & 1023;
    const float* zp = z + b * 65536 + hw;   // z[b][c][h][w], stride 1024 per c

    // token vector, each channel duplicated into both f32x2 lanes
    unsigned long long zpk[64];
    #pragma unroll
    for (int c = 0; c < 64; c++) zpk[c] = dup2(zp[c * 1024]);

    float bestS = 3.4e38f;
    int   bestK = 0;
    int kbase = split * (NE / 2);

    #pragma unroll 1
    for (int t = 0; t < (NE / 2) / TILE; t++) {
        int k0 = kbase + t * TILE;
        __syncthreads();   // previous tile fully consumed
        // transpose-load 64 codes x 64 channels into channel-major smem
        #pragma unroll
        for (int i = 0; i < 8; i++) {
            int idx = i * 128 + tid;       // 0..1023 float4 units
            int j   = idx >> 4;            // code within tile
            int c4  = idx & 15;            // channel group
            float4 v = reinterpret_cast<const float4*>(w + (k0 + j) * DD)[c4];
            sw[(c4 * 4 + 0) * PITCH + j] = v.x;
            sw[(c4 * 4 + 1) * PITCH + j] = v.y;
            sw[(c4 * 4 + 2) * PITCH + j] = v.z;
            sw[(c4 * 4 + 3) * PITCH + j] = v.w;
        }
        if (tid < TILE) swsq[tid] = g_wsq[k0 + tid];
        __syncthreads();

        #pragma unroll 1
        for (int j4 = 0; j4 < TILE / 4; j4++) {
            int j0 = j4 * 4;
            const float* base = sw + j0;
            unsigned long long a0 = 0, a1 = 0, a2 = 0, a3 = 0; // 4 indep chains
            #pragma unroll
            for (int c = 0; c < 64; c += 2) {
                unsigned long long w01e = *reinterpret_cast<const unsigned long long*>(base + c * PITCH);
                unsigned long long w23e = *reinterpret_cast<const unsigned long long*>(base + c * PITCH + 2);
                unsigned long long w01o = *reinterpret_cast<const unsigned long long*>(base + (c + 1) * PITCH);
                unsigned long long w23o = *reinterpret_cast<const unsigned long long*>(base + (c + 1) * PITCH + 2);
                fma2(a0, zpk[c],     w01e);
                fma2(a2, zpk[c],     w23e);
                fma2(a1, zpk[c + 1], w01o);
                fma2(a3, zpk[c + 1], w23o);
            }
            float2 f0 = *reinterpret_cast<float2*>(&a0);
            float2 f1 = *reinterpret_cast<float2*>(&a1);
            float2 f2 = *reinterpret_cast<float2*>(&a2);
            float2 f3 = *reinterpret_cast<float2*>(&a3);
            float d0 = f0.x + f1.x, d1 = f0.y + f1.y;
            float d2 = f2.x + f3.x, d3 = f2.y + f3.y;
            float s0 = swsq[j0]     - 2.f * d0;
            float s1 = swsq[j0 + 1] - 2.f * d1;
            float s2 = swsq[j0 + 2] - 2.f * d2;
            float s3 = swsq[j0 + 3] - 2.f * d3;
            if (s0 < bestS) { bestS = s0; bestK = k0 + j0; }
            if (s1 < bestS) { bestS = s1; bestK = k0 + j0 + 1; }
            if (s2 < bestS) { bestS = s2; bestK = k0 + j0 + 2; }
            if (s3 < bestS) { bestS = s3; bestK = k0 + j0 + 3; }
        }
    }

    // monotone float -> uint encoding; low 32 bits carry code index
    unsigned u = __float_as_uint(bestS);
    u ^= (u & 0x80000000u) ? 0xFFFFFFFFu : 0x80000000u;
    g_part[split][n] = ((unsigned long long)u << 32) | (unsigned)bestK;
}

// -------------------------------------------------- combine + epilogue
__global__ void k_combine(const float* __restrict__ z,
                          const float* __restrict__ w,
                          float* __restrict__ out) {
    int n = blockIdx.x * blockDim.x + threadIdx.x;
    unsigned long long ka = g_part[0][n];
    unsigned long long kb = g_part[1][n];
    unsigned long long key = (ka < kb) ? ka : kb;
    int k = (int)(key & 0xFFFFFFFFull);

    int b  = n >> 10;
    int hw = n & 1023;
    const float* zp = z   + b * 65536 + hw;
    float*       oq = out + OZQ + b * 65536 + hw;
    const float* wr = w + k * DD;

    float lsum = 0.f;
    #pragma unroll
    for (int c = 0; c < 64; c++) {
        float zv = zp[c * 1024];
        float wv = wr[c];
        oq[c * 1024] = wv;                 // straight-through value == z_q
        float dd = wv - zv;
        lsum += dd * dd;
        atomicAdd(&g_emb[k * DD + c], zv); // segment sum of z
    }
    atomicAdd(&g_enc[k], 1.0f);

    #pragma unroll
    for (int o = 16; o; o >>= 1) lsum += __shfl_down_sync(0xFFFFFFFFu, lsum, o);
    if ((threadIdx.x & 31) == 0) atomicAdd(&g_loss, lsum);
}

// -------------------------------------------------- EMA stage 1
__global__ void k_ema1(const float* __restrict__ cs,
                       const float* __restrict__ ea,
                       float* __restrict__ out) {
    int i = blockIdx.x * blockDim.x + threadIdx.x;
    if (i < NE * DD)
        out[OEA + i] = ea[i] * DECAY + (1.f - DECAY) * g_emb[i];
    float v = 0.f;
    if (i < NE) {
        v = cs[i] * DECAY + (1.f - DECAY) * g_enc[i];
        out[OCS + i] = v;
    }
    #pragma unroll
    for (int o = 16; o; o >>= 1) v += __shfl_down_sync(0xFFFFFFFFu, v, o);
    if ((threadIdx.x & 31) == 0 && i < NE) atomicAdd(&g_nsum, v);
}

// -------------------------------------------------- EMA stage 2
__global__ void k_ema2(float* __restrict__ out) {
    int i = blockIdx.x * blockDim.x + threadIdx.x;
    float nn = g_nsum;
    int k = i >> 6;
    float ncs = out[OCS + k];
    float sm  = (ncs + EPSC) / (nn + (float)NE * EPSC) * nn;
    out[OW + i] = out[OEA + i] / sm;
    if (i == 0) out[OLOSS] = BETA * g_loss / (float)(NTOK * DD);
}

// -------------------------------------------------- launch
extern "C" void kernel_launch(void* const* d_in, const int* in_sizes, int n_in,
                              void* d_out, int out_size) {
    const float* z  = (const float*)d_in[0];
    const float* w  = (const float*)d_in[1];
    const float* cs = (const float*)d_in[2];
    const float* ea = (const float*)d_in[3];
    float* out = (float*)d_out;

    k_zero   <<<(NE * DD + 255) / 256, 256>>>();
    k_wsq    <<<(NE * 32) / 256, 256>>>(w);
    k_argmin <<<dim3(NTOK / 128, 2), 128>>>(z, w);
    k_combine<<<NTOK / 256, 256>>>(z, w, out);
    k_ema1   <<<(NE * DD) / 256, 256>>>(cs, ea, out);
    k_ema2   <<<(NE * DD) / 256, 256>>>(out);
}

// round 6
// speedup vs baseline: 2.2591x; 2.2591x over previous
#include <cuda_runtime.h>
#include <cuda_fp16.h>
#include <cuda_bf16.h>
#include <cstdint>

#define NE   8192
#define DD   64
#define NTOK 16384
#define BETA  0.25f
#define DECAY 0.99f
#define EPSC  1e-5f

// output layout (concatenated, float32)
#define OZQ   0
#define OLOSS 1048576
#define OW    1048577
#define OCS   1572865
#define OEA   1581057

#define MARGIN 6.0f

// ------------------------------------------------------------- device scratch
__device__ float g_wsq[NE];
__device__ float g_min[NTOK];
__device__ int   g_idx[NTOK];
__device__ float g_enc[NE];
__device__ float g_emb[NE * DD];
__device__ float g_loss;
__device__ float g_nsum;
__device__ __nv_bfloat16 g_w1[NE * DD];
__device__ __nv_bfloat16 g_z1[NTOK * DD];
__device__ __half g_scores[(size_t)NTOK * NE];   // 268 MB coarse score matrix

// ------------------------------------------------------------- helpers
__device__ __forceinline__ uint32_t smem_u32(const void* p) {
    uint32_t a;
    asm("{ .reg .u64 t; cvta.to.shared.u64 t, %1; cvt.u32.u64 %0, t; }" : "=r"(a) : "l"(p));
    return a;
}
#define SWZ(b) ((b) ^ (((b) >> 3) & 0x70))

#define LDMX4(r0, r1, r2, r3, a) \
    asm volatile("ldmatrix.sync.aligned.m8n8.x4.shared.b16 {%0,%1,%2,%3}, [%4];" \
                 : "=r"(r0), "=r"(r1), "=r"(r2), "=r"(r3) : "r"(a))

#define MMA16816(d, a, b0, b1) \
    asm volatile("mma.sync.aligned.m16n8k16.row.col.f32.bf16.bf16.f32 " \
                 "{%0,%1,%2,%3},{%4,%5,%6,%7},{%8,%9},{%0,%1,%2,%3};" \
                 : "+f"((d)[0]), "+f"((d)[1]), "+f"((d)[2]), "+f"((d)[3]) \
                 : "r"((a)[0]), "r"((a)[1]), "r"((a)[2]), "r"((a)[3]), \
                   "r"(b0), "r"(b1))

#define CP_ASYNC16(dst, src) \
    asm volatile("cp.async.cg.shared.global [%0], [%1], 16;" :: "r"(dst), "l"(src))
#define CP_COMMIT() asm volatile("cp.async.commit_group;" ::: "memory")

// ------------------------------------------------------------- zero pass
__global__ void k_zero() {
    int i = blockIdx.x * blockDim.x + threadIdx.x;
    if (i < NE * DD) g_emb[i] = 0.f;
    if (i < NE)      g_enc[i] = 0.f;
    if (i == 0) { g_loss = 0.f; g_nsum = 0.f; }
}

// ------------------------------------------------------------- |w_k|^2 (fp32 exact)
__global__ void k_wsq(const float* __restrict__ w) {
    int gt   = blockIdx.x * blockDim.x + threadIdx.x;
    int row  = gt >> 5;
    int lane = gt & 31;
    if (row >= NE) return;
    const float* r = w + row * DD;
    float a = r[lane], b2 = r[lane + 32];
    float s = a * a + b2 * b2;
    #pragma unroll
    for (int o = 16; o; o >>= 1) s += __shfl_down_sync(0xFFFFFFFFu, s, o);
    if (lane == 0) g_wsq[row] = s;
}

// ------------------------------------------------------------- bf16 preps
__global__ void k_prep_w(const float* __restrict__ w) {
    int i = blockIdx.x * blockDim.x + threadIdx.x;
    if (i < NE * DD) g_w1[i] = __float2bfloat16(w[i]);
}

__global__ __launch_bounds__(256) void k_prep_z(const float* __restrict__ z) {
    __shared__ float tile[64 * 130];
    int n0 = blockIdx.x * 128;
    int b  = n0 >> 10;
    int hw0 = n0 & 1023;
    for (int idx = threadIdx.x; idx < 8192; idx += 256) {
        int c = idx >> 7, i = idx & 127;
        tile[c * 130 + i] = z[b * 65536 + c * 1024 + hw0 + i];
    }
    __syncthreads();
    for (int idx = threadIdx.x; idx < 8192; idx += 256) {
        int t = idx >> 6, c = idx & 63;
        g_z1[(n0 + t) * 64 + c] = __float2bfloat16(tile[c * 130 + t]);
    }
}

// ------------------------------------------------------------- coarse HMMA GEMM
// smem: A 16KB | B double-buffer 2x16KB | wsq 32KB
#define SM_A   0
#define SM_B   16384
#define SM_WSQ 49152
#define SM_TOT 81920

__device__ __forceinline__ void load_b_tile(uint32_t smb, int t, int buf, int tid) {
    #pragma unroll
    for (int i = 0; i < 4; i++) {
        int idx = i * 256 + tid;
        int row = idx >> 3, c = idx & 7;
        uint32_t dst = smb + SM_B + buf * 16384 + SWZ(row * 128 + c * 16);
        const void* src = g_w1 + (t * 128 + row) * 64 + c * 8;
        CP_ASYNC16(dst, src);
    }
    CP_COMMIT();
}

__global__ __launch_bounds__(256) void k_coarse() {
    extern __shared__ char sm[];
    uint32_t smb = smem_u32(sm);
    const int tid = threadIdx.x, lane = tid & 31, w = tid >> 5;
    const int tok0 = blockIdx.x * 128;

    // wsq preload (all 8192 floats)
    #pragma unroll
    for (int i = 0; i < 8; i++) {
        int idx = i * 256 + tid;
        reinterpret_cast<uint4*>(sm + SM_WSQ)[idx] =
            reinterpret_cast<const uint4*>(g_wsq)[idx];
    }
    // A tile: 128 tokens x 64 ch, bf16, swizzled
    #pragma unroll
    for (int i = 0; i < 4; i++) {
        int idx = i * 256 + tid;
        int row = idx >> 3, c = idx & 7;
        uint4 v = reinterpret_cast<const uint4*>(g_z1)[(tok0 + row) * 8 + c];
        *reinterpret_cast<uint4*>(sm + SM_A + SWZ(row * 128 + c * 16)) = v;
    }
    load_b_tile(smb, 0, 0, tid);
    load_b_tile(smb, 1, 1, tid);
    __syncthreads();

    // A fragments (held in registers whole kernel)
    uint32_t afr[4][4];
    {
        int grp = lane >> 3, lr = lane & 7;
        #pragma unroll
        for (int c = 0; c < 4; c++) {
            int row = w * 16 + ((grp & 1) ? 8 : 0) + lr;
            int kb  = c * 32 + ((grp & 2) ? 16 : 0);
            uint32_t ad = smb + SM_A + SWZ(row * 128 + kb);
            LDMX4(afr[c][0], afr[c][1], afr[c][2], afr[c][3], ad);
        }
    }

    float best0 = 3.4e38f, best1 = 3.4e38f;
    const int q = lane & 3, r = lane >> 2;
    const int row0 = tok0 + w * 16 + r;

    #pragma unroll 1
    for (int t = 0; t < 64; t++) {
        if (t < 63) asm volatile("cp.async.wait_group 1;" ::: "memory");
        else        asm volatile("cp.async.wait_group 0;" ::: "memory");
        __syncthreads();

        uint32_t bb = smb + SM_B + (t & 1) * 16384;
        float acc[16][4];
        #pragma unroll
        for (int j = 0; j < 16; j++)
            #pragma unroll
            for (int e = 0; e < 4; e++) acc[j][e] = 0.f;

        int lr = lane & 7, grp = lane >> 3;
        int koff = (grp & 1) * 16 + (grp >> 1) * 32;
        #pragma unroll
        for (int j = 0; j < 16; j++) {
            int rowb = j * 8 + lr;
            uint32_t b0, b1, b2, b3, b4, b5, b6, b7;
            LDMX4(b0, b1, b2, b3, bb + SWZ(rowb * 128 + koff));
            LDMX4(b4, b5, b6, b7, bb + SWZ(rowb * 128 + 64 + koff));
            MMA16816(acc[j], afr[0], b0, b1);
            MMA16816(acc[j], afr[1], b2, b3);
            MMA16816(acc[j], afr[2], b4, b5);
            MMA16816(acc[j], afr[3], b6, b7);
        }
        __syncthreads();                    // all reads of buf t&1 done
        if (t + 2 < 64) load_b_tile(smb, t + 2, t & 1, tid);

        // epilogue: scores, running min, fp16 store
        const float2* wsqp = reinterpret_cast<const float2*>(sm + SM_WSQ);
        #pragma unroll
        for (int j = 0; j < 16; j++) {
            int col = t * 128 + j * 8 + 2 * q;
            float2 ws = wsqp[col >> 1];
            float s00 = fmaf(acc[j][0], -2.f, ws.x);
            float s01 = fmaf(acc[j][1], -2.f, ws.y);
            float s10 = fmaf(acc[j][2], -2.f, ws.x);
            float s11 = fmaf(acc[j][3], -2.f, ws.y);
            best0 = fminf(best0, fminf(s00, s01));
            best1 = fminf(best1, fminf(s10, s11));
            __half2 h0 = __floats2half2_rn(s00, s01);
            __half2 h1 = __floats2half2_rn(s10, s11);
            *reinterpret_cast<__half2*>(g_scores + (size_t)row0 * NE + col)       = h0;
            *reinterpret_cast<__half2*>(g_scores + (size_t)(row0 + 8) * NE + col) = h1;
        }
    }

    // per-token min: reduce over the 4 lanes of each quad
    #pragma unroll
    for (int o = 1; o <= 2; o <<= 1) {
        best0 = fminf(best0, __shfl_xor_sync(0xFFFFFFFFu, best0, o));
        best1 = fminf(best1, __shfl_xor_sync(0xFFFFFFFFu, best1, o));
    }
    if (q == 0) {
        g_min[row0]     = best0;
        g_min[row0 + 8] = best1;
    }
}

// ------------------------------------------------------------- select (scan + exact refine)
__device__ __forceinline__ unsigned long long refine_min(
        unsigned long long best, const float* zp, const float* w, int k) {
    const float* wr = w + k * DD;
    float dot = 0.f;
    #pragma unroll
    for (int c = 0; c < DD; c++) dot = fmaf(zp[c << 10], wr[c], dot);
    float d = fmaf(dot, -2.f, g_wsq[k]);
    uint32_t u = __float_as_uint(d);
    u ^= (u & 0x80000000u) ? 0xFFFFFFFFu : 0x80000000u;
    unsigned long long key = ((unsigned long long)u << 32) | (uint32_t)k;
    return key < best ? key : best;
}

__global__ __launch_bounds__(256) void k_select(const float* __restrict__ z,
                                                const float* __restrict__ w) {
    int gt   = blockIdx.x * blockDim.x + threadIdx.x;
    int n    = gt >> 5;
    int lane = gt & 31;
    float thr = g_min[n] + MARGIN;
    const uint4* sp = reinterpret_cast<const uint4*>(g_scores + (size_t)n * NE);
    const float* zp = z + (n >> 10) * 65536 + (n & 1023);
    unsigned long long best = ~0ull;

    #pragma unroll 1
    for (int i = 0; i < 32; i++) {
        uint4 v = __ldcs(sp + i * 32 + lane);
        uint32_t ws[4] = { v.x, v.y, v.z, v.w };
        int k0 = (i * 32 + lane) * 8;
        #pragma unroll
        for (int h = 0; h < 4; h++) {
            __half2 hv = *reinterpret_cast<__half2*>(&ws[h]);
            float s0 = __low2float(hv), s1 = __high2float(hv);
            if (s0 < thr) best = refine_min(best, zp, w, k0 + h * 2);
            if (s1 < thr) best = refine_min(best, zp, w, k0 + h * 2 + 1);
        }
    }
    #pragma unroll
    for (int o = 16; o; o >>= 1) {
        unsigned long long v = __shfl_xor_sync(0xFFFFFFFFu, best, o);
        if (v < best) best = v;
    }
    if (lane == 0) g_idx[n] = (int)(best & 0xFFFFFFFFull);
}

// ------------------------------------------------------------- combine + epilogue
__global__ void k_combine(const float* __restrict__ z,
                          const float* __restrict__ w,
                          float* __restrict__ out) {
    int n = blockIdx.x * blockDim.x + threadIdx.x;
    int k = g_idx[n];

    int b  = n >> 10;
    int hw = n & 1023;
    const float* zp = z   + b * 65536 + hw;
    float*       oq = out + OZQ + b * 65536 + hw;
    const float* wr = w + k * DD;

    float lsum = 0.f;
    #pragma unroll
    for (int c = 0; c < 64; c++) {
        float zv = zp[c * 1024];
        float wv = wr[c];
        oq[c * 1024] = wv;
        float dd = wv - zv;
        lsum += dd * dd;
        atomicAdd(&g_emb[k * DD + c], zv);
    }
    atomicAdd(&g_enc[k], 1.0f);

    #pragma unroll
    for (int o = 16; o; o >>= 1) lsum += __shfl_down_sync(0xFFFFFFFFu, lsum, o);
    if ((threadIdx.x & 31) == 0) atomicAdd(&g_loss, lsum);
}

// ------------------------------------------------------------- EMA stage 1
__global__ void k_ema1(const float* __restrict__ cs,
                       const float* __restrict__ ea,
                       float* __restrict__ out) {
    int i = blockIdx.x * blockDim.x + threadIdx.x;
    if (i < NE * DD)
        out[OEA + i] = ea[i] * DECAY + (1.f - DECAY) * g_emb[i];
    float v = 0.f;
    if (i < NE) {
        v = cs[i] * DECAY + (1.f - DECAY) * g_enc[i];
        out[OCS + i] = v;
    }
    #pragma unroll
    for (int o = 16; o; o >>= 1) v += __shfl_down_sync(0xFFFFFFFFu, v, o);
    if ((threadIdx.x & 31) == 0 && i < NE) atomicAdd(&g_nsum, v);
}

// ------------------------------------------------------------- EMA stage 2
__global__ void k_ema2(float* __restrict__ out) {
    int i = blockIdx.x * blockDim.x + threadIdx.x;
    float nn = g_nsum;
    int k = i >> 6;
    float ncs = out[OCS + k];
    float sm  = (ncs + EPSC) / (nn + (float)NE * EPSC) * nn;
    out[OW + i] = out[OEA + i] / sm;
    if (i == 0) out[OLOSS] = BETA * g_loss / (float)(NTOK * DD);
}

// ------------------------------------------------------------- launch
extern "C" void kernel_launch(void* const* d_in, const int* in_sizes, int n_in,
                              void* d_out, int out_size) {
    const float* z  = (const float*)d_in[0];
    const float* w  = (const float*)d_in[1];
    const float* cs = (const float*)d_in[2];
    const float* ea = (const float*)d_in[3];
    float* out = (float*)d_out;

    cudaFuncSetAttribute(k_coarse, cudaFuncAttributeMaxDynamicSharedMemorySize, SM_TOT);

    k_zero   <<<(NE * DD + 255) / 256, 256>>>();
    k_wsq    <<<(NE * 32) / 256, 256>>>(w);
    k_prep_w <<<(NE * DD + 255) / 256, 256>>>(w);
    k_prep_z <<<NTOK / 128, 256>>>(z);
    k_coarse <<<NTOK / 128, 256, SM_TOT>>>();
    k_select <<<(NTOK * 32) / 256, 256>>>(z, w);
    k_combine<<<NTOK / 256, 256>>>(z, w, out);
    k_ema1   <<<(NE * DD) / 256, 256>>>(cs, ea, out);
    k_ema2   <<<(NE * DD) / 256, 256>>>(out);
}